// round 7
// baseline (speedup 1.0000x reference)
#include <cuda_runtime.h>
#include <cuda_fp16.h>
#include <cstdint>

#define NTHREADS 256

// ---------------- smem layout (bytes, per CTA) ----------------
// W half (128 n-rows): hi 32KB + lo 32KB ; A: 2 buffers x 16KB (64 rows x 256B)
static constexpr int SM_WHI   = 0;
static constexpr int SM_WLO   = 32768;
static constexpr int SM_A     = 65536;
static constexpr int A_BUF_SZ = 16384;
static constexpr int SMEM_TOTAL = 98304;   // 96KB -> 2 CTAs/SM

// ---------------- helpers ----------------
__device__ __forceinline__ uint32_t smem_u32(const void* p) {
    uint32_t a;
    asm("{ .reg .u64 t; cvta.to.shared.u64 t, %1; cvt.u32.u64 %0, t; }"
        : "=r"(a) : "l"(p));
    return a;
}

__device__ __forceinline__ void ldsm_x4(uint32_t& r0, uint32_t& r1,
                                        uint32_t& r2, uint32_t& r3, uint32_t addr) {
    asm volatile("ldmatrix.sync.aligned.m8n8.x4.shared.b16 {%0,%1,%2,%3}, [%4];"
                 : "=r"(r0), "=r"(r1), "=r"(r2), "=r"(r3) : "r"(addr));
}

__device__ __forceinline__ void mma_f16(float* c, const uint32_t* a,
                                        uint32_t b0, uint32_t b1) {
    asm volatile(
        "mma.sync.aligned.m16n8k16.row.col.f32.f16.f16.f32 "
        "{%0,%1,%2,%3}, {%4,%5,%6,%7}, {%8,%9}, {%0,%1,%2,%3};"
        : "+f"(c[0]), "+f"(c[1]), "+f"(c[2]), "+f"(c[3])
        : "r"(a[0]), "r"(a[1]), "r"(a[2]), "r"(a[3]), "r"(b0), "r"(b1));
}

// convert 8 consecutive fp32 -> 16B of fp16
__device__ __forceinline__ uint4 cvt8(float4 v0, float4 v1) {
    __half2 h0 = __floats2half2_rn(v0.x, v0.y);
    __half2 h1 = __floats2half2_rn(v0.z, v0.w);
    __half2 h2 = __floats2half2_rn(v1.x, v1.y);
    __half2 h3 = __floats2half2_rn(v1.z, v1.w);
    uint4 r;
    r.x = *(uint32_t*)&h0; r.y = *(uint32_t*)&h1;
    r.z = *(uint32_t*)&h2; r.w = *(uint32_t*)&h3;
    return r;
}

// split 8 fp32 -> fp16 hi + fp16 lo (W only, done once)
__device__ __forceinline__ void splitW8(float4 v0, float4 v1, uint4& hi, uint4& lo) {
    __half2 h0 = __floats2half2_rn(v0.x, v0.y);
    __half2 h1 = __floats2half2_rn(v0.z, v0.w);
    __half2 h2 = __floats2half2_rn(v1.x, v1.y);
    __half2 h3 = __floats2half2_rn(v1.z, v1.w);
    __half2 l0 = __floats2half2_rn(v0.x - __low2float(h0), v0.y - __high2float(h0));
    __half2 l1 = __floats2half2_rn(v0.z - __low2float(h1), v0.w - __high2float(h1));
    __half2 l2 = __floats2half2_rn(v1.x - __low2float(h2), v1.y - __high2float(h2));
    __half2 l3 = __floats2half2_rn(v1.z - __low2float(h3), v1.w - __high2float(h3));
    hi.x = *(uint32_t*)&h0; hi.y = *(uint32_t*)&h1;
    hi.z = *(uint32_t*)&h2; hi.w = *(uint32_t*)&h3;
    lo.x = *(uint32_t*)&l0; lo.y = *(uint32_t*)&l1;
    lo.z = *(uint32_t*)&l2; lo.w = *(uint32_t*)&l3;
}

// ---------------- kernel ----------------
// A = feat[::2] as [M = 8192*64, K=128] fp32 ; B = W [N=256, K=128]
// CTA pair (2t, 2t+1) shares A tile t; each CTA computes one N-half (128 cols)
// D = A_fp16 * (Bhi + Blo)^T + bias  (2 fp16 MMA chains, fp32 accum)
__global__ void __launch_bounds__(NTHREADS, 2)
decomp_kernel(const float* __restrict__ feat, const float* __restrict__ W,
              const float* __restrict__ bias, float* __restrict__ out, int num_tiles) {
    extern __shared__ char smem[];
    const uint32_t sb = smem_u32(smem);
    const int tid = threadIdx.x;
    const int lane = tid & 31;
    const int wid = tid >> 5;

    const int nhalf  = blockIdx.x & 1;          // output half (0: y1, 1: y2)
    const int pair   = blockIdx.x >> 1;
    const int npairs = gridDim.x >> 1;

    const int warp_m = wid & 1;        // 0..1  (m block of 32)
    const int warp_n = wid >> 1;       // 0..3  (n block of 32 within the half)

    // ---- stage W half -> fp16 hi/lo swizzled smem (once) ----
    for (int it = 0; it < 8; it++) {
        int idx = tid + it * NTHREADS;        // 0..2047
        int row = idx >> 4;                   // local n row 0..127
        int ch  = idx & 15;                   // 16B fp16 chunk within row
        const float4* g = (const float4*)(W + (nhalf * 128 + row) * 128 + ch * 8);
        uint4 hi, lo;
        splitW8(g[0], g[1], hi, lo);
        int phys = ch ^ (row & 7);
        *(uint4*)(smem + SM_WHI + row * 256 + phys * 16) = hi;
        *(uint4*)(smem + SM_WLO + row * 256 + phys * 16) = lo;
    }

    // ---- preload first A tile into buf 0 (64 rows x 128 fp32 -> fp16) ----
    {
        int t0 = pair;
#pragma unroll
        for (int it = 0; it < 4; it++) {
            int idx = tid + it * NTHREADS;    // 0..1023
            int row = idx >> 4;               // tile row 0..63
            int ch  = idx & 15;
            long f = (long)(t0 * 8 + (row >> 3)) * 2048 + (row & 7) * 128 + ch * 8;
            const float4* g = (const float4*)(feat + f);
            uint4 h = cvt8(g[0], g[1]);
            int phys = ch ^ (row & 7);
            *(uint4*)(smem + SM_A + row * 256 + phys * 16) = h;
        }
    }

    // ---- bias fragments (persistent registers) ----
    float2 bfr[4];
#pragma unroll
    for (int nf = 0; nf < 4; nf++) {
        int n_global = nhalf * 128 + warp_n * 32 + nf * 8 + ((lane & 3) << 1);
        bfr[nf] = *(const float2*)(bias + n_global);
    }

    // ---- per-thread ldmatrix address components ----
    const int blk = lane >> 3;          // 0..3
    const int rin = lane & 7;
    const int a_mrow_base = warp_m * 32 + ((blk & 1) << 3) + rin; // + mt*16
    const int a_khalf = blk >> 1;
    const int b_nrow_base = warp_n * 32 + ((blk >> 1) << 3) + rin; // + np*16
    const int b_khalf = blk & 1;

    __syncthreads();

    int buf = 0;
    for (int t = pair; t < num_tiles; t += npairs, buf ^= 1) {
        const int tn = t + npairs;
        const bool has_next = tn < num_tiles;
        const uint32_t abuf = sb + SM_A + buf * A_BUF_SZ;
        const uint32_t nbuf = (uint32_t)(SM_A + (buf ^ 1) * A_BUF_SZ);

        // ---- next tile's global loads: one wave, 32 regs ----
        float4 va[4][2];
        if (has_next) {
#pragma unroll
            for (int it = 0; it < 4; it++) {
                int idx = tid + it * NTHREADS;
                int row = idx >> 4;
                int ch  = idx & 15;
                long f = (long)(tn * 8 + (row >> 3)) * 2048 + (row & 7) * 128 + ch * 8;
                const float4* g = (const float4*)(feat + f);
                va[it][0] = g[0];
                va[it][1] = g[1];
            }
        }

        float c[2][4][4];
#pragma unroll
        for (int mt = 0; mt < 2; mt++)
#pragma unroll
            for (int nf = 0; nf < 4; nf++)
#pragma unroll
                for (int r = 0; r < 4; r++) c[mt][nf][r] = 0.0f;

#pragma unroll
        for (int ks = 0; ks < 8; ks++) {
            uint32_t ah[2][4];
#pragma unroll
            for (int mt = 0; mt < 2; mt++) {
                int mrow = a_mrow_base + mt * 16;
                int kc = ks * 2 + a_khalf;
                uint32_t off = (uint32_t)(mrow * 256 + (kc ^ (mrow & 7)) * 16);
                ldsm_x4(ah[mt][0], ah[mt][1], ah[mt][2], ah[mt][3], abuf + off);
            }
#pragma unroll
            for (int np = 0; np < 2; np++) {
                int nrow = b_nrow_base + np * 16;
                int kc = ks * 2 + b_khalf;
                uint32_t off = (uint32_t)(nrow * 256 + (kc ^ (nrow & 7)) * 16);
                uint32_t bh[4], bl[4];
                ldsm_x4(bh[0], bh[1], bh[2], bh[3], sb + SM_WHI + off);
                ldsm_x4(bl[0], bl[1], bl[2], bl[3], sb + SM_WLO + off);
#pragma unroll
                for (int mt = 0; mt < 2; mt++) {
                    mma_f16(c[mt][2 * np],     ah[mt], bh[0], bh[1]);
                    mma_f16(c[mt][2 * np + 1], ah[mt], bh[2], bh[3]);
                    mma_f16(c[mt][2 * np],     ah[mt], bl[0], bl[1]);
                    mma_f16(c[mt][2 * np + 1], ah[mt], bl[2], bl[3]);
                }
            }

            // ---- flush prefetched A into other buffer (LDGs ~640cyc old) ----
            if (ks == 5 && has_next) {
#pragma unroll
                for (int it = 0; it < 4; it++) {
                    int idx = tid + it * NTHREADS;
                    int row = idx >> 4;
                    int ch  = idx & 15;
                    uint4 h = cvt8(va[it][0], va[it][1]);
                    int phys = ch ^ (row & 7);
                    *(uint4*)(smem + nbuf + row * 256 + phys * 16) = h;
                }
            }
        }

        // ================= epilogue: bias + direct stores ==================
#pragma unroll
        for (int mt = 0; mt < 2; mt++) {
            int m_local = warp_m * 32 + mt * 16 + (lane >> 2);
            long m_global = (long)t * 64 + m_local;
            long i0 = m_global >> 3;
            int ci = (int)(m_global & 7);
            long base0 = ((i0 << 4) + (nhalf << 3) + ci) * 128;
#pragma unroll
            for (int nf = 0; nf < 4; nf++) {
                int o = warp_n * 32 + nf * 8 + ((lane & 3) << 1);
                float2 v0, v1;
                v0.x = c[mt][nf][0] + bfr[nf].x;
                v0.y = c[mt][nf][1] + bfr[nf].y;
                v1.x = c[mt][nf][2] + bfr[nf].x;
                v1.y = c[mt][nf][3] + bfr[nf].y;
                *(float2*)(out + base0 + o) = v0;          // row m_local
                *(float2*)(out + base0 + 2048 + o) = v1;   // row m_local + 8
            }
        }

        // converts(nbuf) visible before next tile's ldsm
        __syncthreads();
    }
}

// ---------------- launch ----------------
extern "C" void kernel_launch(void* const* d_in, const int* in_sizes, int n_in,
                              void* d_out, int out_size) {
    const float* feat = (const float*)d_in[0];
    const float* W    = (const float*)d_in[1];
    const float* b    = (const float*)d_in[2];
    float* out        = (float*)d_out;

    const int n = in_sizes[0] / (8 * 128);   // 131072
    const int tiles = n / 16;                // 64 A-rows per tile -> 8192

    cudaFuncSetAttribute(decomp_kernel, cudaFuncAttributeMaxDynamicSharedMemorySize,
                         SMEM_TOTAL);
    int dev = 0;
    cudaGetDevice(&dev);
    int sms = 148;
    cudaDeviceGetAttribute(&sms, cudaDevAttrMultiProcessorCount, dev);
    int pairs = sms < tiles ? sms : tiles;
    int grid = pairs * 2;

    decomp_kernel<<<grid, NTHREADS, SMEM_TOTAL>>>(feat, W, b, out, tiles);
}

// round 8
// speedup vs baseline: 1.4858x; 1.4858x over previous
#include <cuda_runtime.h>
#include <cuda_fp16.h>
#include <cstdint>

#define NTHREADS 256

// ---------------- smem layout (bytes) ----------------
// W: 256 rows x 256B (fp16) = 64KB ; A: 2 buffers x 32KB (128 rows x 256B fp16)
static constexpr int SM_WHI   = 0;
static constexpr int SM_A     = 65536;
static constexpr int A_BUF_SZ = 32768;
static constexpr int SMEM_TOTAL = 131072;

// ---------------- helpers ----------------
__device__ __forceinline__ uint32_t smem_u32(const void* p) {
    uint32_t a;
    asm("{ .reg .u64 t; cvta.to.shared.u64 t, %1; cvt.u32.u64 %0, t; }"
        : "=r"(a) : "l"(p));
    return a;
}

__device__ __forceinline__ void ldsm_x4(uint32_t& r0, uint32_t& r1,
                                        uint32_t& r2, uint32_t& r3, uint32_t addr) {
    asm volatile("ldmatrix.sync.aligned.m8n8.x4.shared.b16 {%0,%1,%2,%3}, [%4];"
                 : "=r"(r0), "=r"(r1), "=r"(r2), "=r"(r3) : "r"(addr));
}

__device__ __forceinline__ void mma_f16(float* c, const uint32_t* a,
                                        uint32_t b0, uint32_t b1) {
    asm volatile(
        "mma.sync.aligned.m16n8k16.row.col.f32.f16.f16.f32 "
        "{%0,%1,%2,%3}, {%4,%5,%6,%7}, {%8,%9}, {%0,%1,%2,%3};"
        : "+f"(c[0]), "+f"(c[1]), "+f"(c[2]), "+f"(c[3])
        : "r"(a[0]), "r"(a[1]), "r"(a[2]), "r"(a[3]), "r"(b0), "r"(b1));
}

// convert 8 consecutive fp32 -> 16B of fp16
__device__ __forceinline__ uint4 cvt8(float4 v0, float4 v1) {
    __half2 h0 = __floats2half2_rn(v0.x, v0.y);
    __half2 h1 = __floats2half2_rn(v0.z, v0.w);
    __half2 h2 = __floats2half2_rn(v1.x, v1.y);
    __half2 h3 = __floats2half2_rn(v1.z, v1.w);
    uint4 r;
    r.x = *(uint32_t*)&h0; r.y = *(uint32_t*)&h1;
    r.z = *(uint32_t*)&h2; r.w = *(uint32_t*)&h3;
    return r;
}

// ---------------- kernel ----------------
// A = feat[::2] as [M = 4096*128, K=128] fp32 ; B = W [N=256, K=128]
// D = A_fp16 * B_fp16^T + bias  (single fp16 MMA chain, fp32 accum)
__global__ void __launch_bounds__(NTHREADS, 1)
decomp_kernel(const float* __restrict__ feat, const float* __restrict__ W,
              const float* __restrict__ bias, float* __restrict__ out, int num_tiles) {
    extern __shared__ char smem[];
    const uint32_t sb = smem_u32(smem);
    const int tid = threadIdx.x;
    const int lane = tid & 31;
    const int wid = tid >> 5;

    const int warp_m = wid & 1;        // 0..1  (m block of 64)
    const int warp_n = wid >> 1;       // 0..3  (n block of 64)

    // ---- stage W -> fp16 swizzled smem (once) ----
    for (int it = 0; it < 16; it++) {
        int idx = tid + it * NTHREADS;        // 0..4095
        int row = idx >> 4;                   // n row 0..255
        int ch  = idx & 15;                   // 16B fp16 chunk within row
        const float4* g = (const float4*)(W + row * 128 + ch * 8);
        uint4 h = cvt8(g[0], g[1]);
        int phys = ch ^ (row & 7);
        *(uint4*)(smem + SM_WHI + row * 256 + phys * 16) = h;
    }

    // ---- preload first A tile into buf 0 (128 rows x 128 fp32 -> fp16) ----
    {
        int t0 = blockIdx.x;
#pragma unroll
        for (int it = 0; it < 8; it++) {
            int idx = tid + it * NTHREADS;    // 0..2047
            int row = idx >> 4;               // tile row 0..127
            int ch  = idx & 15;
            long f = (long)(t0 * 16 + (row >> 3)) * 2048 + (row & 7) * 128 + ch * 8;
            const float4* g = (const float4*)(feat + f);
            uint4 h = cvt8(g[0], g[1]);
            int phys = ch ^ (row & 7);
            *(uint4*)(smem + SM_A + row * 256 + phys * 16) = h;
        }
    }

    // ---- bias fragments (persistent registers) ----
    float2 bfr[8];
#pragma unroll
    for (int nf = 0; nf < 8; nf++) {
        int n_global = warp_n * 64 + nf * 8 + ((lane & 3) << 1);
        bfr[nf] = *(const float2*)(bias + n_global);
    }

    // ---- per-thread ldmatrix address components ----
    const int blk = lane >> 3;          // 0..3
    const int rin = lane & 7;
    const int a_mrow_base = warp_m * 64 + ((blk & 1) << 3) + rin; // + mt*16
    const int a_khalf = blk >> 1;
    const int b_nrow_base = warp_n * 64 + ((blk >> 1) << 3) + rin; // + np*16
    const int b_khalf = blk & 1;

    const int out_h = warp_n >> 1;
    const int out_obase = (warp_n & 1) * 64;

    __syncthreads();

    int buf = 0;
    for (int t = blockIdx.x; t < num_tiles; t += gridDim.x, buf ^= 1) {
        const int tn = t + gridDim.x;
        const bool has_next = tn < num_tiles;
        const uint32_t abuf = sb + SM_A + buf * A_BUF_SZ;
        const uint32_t nbuf = (uint32_t)(SM_A + (buf ^ 1) * A_BUF_SZ);

        // ---- wave 1 of next tile's global loads (32 regs) ----
        float4 va[4][2];
        if (has_next) {
#pragma unroll
            for (int it = 0; it < 4; it++) {
                int idx = tid + it * NTHREADS;
                int row = idx >> 4;
                int ch  = idx & 15;
                long f = (long)(tn * 16 + (row >> 3)) * 2048 + (row & 7) * 128 + ch * 8;
                const float4* g = (const float4*)(feat + f);
                va[it][0] = g[0];
                va[it][1] = g[1];
            }
        }

        float c[4][8][4];
#pragma unroll
        for (int mt = 0; mt < 4; mt++)
#pragma unroll
            for (int nf = 0; nf < 8; nf++)
#pragma unroll
                for (int r = 0; r < 4; r++) c[mt][nf][r] = 0.0f;

#pragma unroll
        for (int ks = 0; ks < 8; ks++) {
            uint32_t ah[4][4];
#pragma unroll
            for (int mt = 0; mt < 4; mt++) {
                int mrow = a_mrow_base + mt * 16;
                int kc = ks * 2 + a_khalf;
                uint32_t off = (uint32_t)(mrow * 256 + (kc ^ (mrow & 7)) * 16);
                ldsm_x4(ah[mt][0], ah[mt][1], ah[mt][2], ah[mt][3], abuf + off);
            }
#pragma unroll
            for (int np = 0; np < 4; np++) {
                int nrow = b_nrow_base + np * 16;
                int kc = ks * 2 + b_khalf;
                uint32_t off = (uint32_t)(nrow * 256 + (kc ^ (nrow & 7)) * 16);
                uint32_t bh[4];
                ldsm_x4(bh[0], bh[1], bh[2], bh[3], sb + SM_WHI + off);
#pragma unroll
                for (int mt = 0; mt < 4; mt++) {
                    mma_f16(c[mt][2 * np],     ah[mt], bh[0], bh[1]);
                    mma_f16(c[mt][2 * np + 1], ah[mt], bh[2], bh[3]);
                }
            }

            // ---- mid-loop: flush wave 1, issue wave 2 (LDGs hidden under MMA) ----
            if (ks == 3 && has_next) {
#pragma unroll
                for (int it = 0; it < 4; it++) {
                    int idx = tid + it * NTHREADS;
                    int row = idx >> 4;
                    int ch  = idx & 15;
                    uint4 h = cvt8(va[it][0], va[it][1]);
                    int phys = ch ^ (row & 7);
                    *(uint4*)(smem + nbuf + row * 256 + phys * 16) = h;
                }
#pragma unroll
                for (int it = 0; it < 4; it++) {
                    int idx = tid + (it + 4) * NTHREADS;
                    int row = idx >> 4;
                    int ch  = idx & 15;
                    long f = (long)(tn * 16 + (row >> 3)) * 2048 + (row & 7) * 128 + ch * 8;
                    const float4* g = (const float4*)(feat + f);
                    va[it][0] = g[0];
                    va[it][1] = g[1];
                }
            }
        }

        // ---- flush wave 2 ----
        if (has_next) {
#pragma unroll
            for (int it = 0; it < 4; it++) {
                int idx = tid + (it + 4) * NTHREADS;
                int row = idx >> 4;
                int ch  = idx & 15;
                uint4 h = cvt8(va[it][0], va[it][1]);
                int phys = ch ^ (row & 7);
                *(uint4*)(smem + nbuf + row * 256 + phys * 16) = h;
            }
        }

        // ================= epilogue: bias + direct stores ==================
#pragma unroll
        for (int mt = 0; mt < 4; mt++) {
            int m_local = warp_m * 64 + mt * 16 + (lane >> 2);
            long m_global = (long)t * 128 + m_local;
            long i0 = m_global >> 3;
            int ci = (int)(m_global & 7);
            long base0 = ((i0 << 4) + (out_h << 3) + ci) * 128;
#pragma unroll
            for (int nf = 0; nf < 8; nf++) {
                int o = out_obase + nf * 8 + ((lane & 3) << 1);
                float2 v0, v1;
                v0.x = c[mt][nf][0] + bfr[nf].x;
                v0.y = c[mt][nf][1] + bfr[nf].y;
                v1.x = c[mt][nf][2] + bfr[nf].x;
                v1.y = c[mt][nf][3] + bfr[nf].y;
                *(float2*)(out + base0 + o) = v0;          // row m_local
                *(float2*)(out + base0 + 2048 + o) = v1;   // row m_local + 8
            }
        }

        __syncthreads();
    }
}

// ---------------- launch ----------------
extern "C" void kernel_launch(void* const* d_in, const int* in_sizes, int n_in,
                              void* d_out, int out_size) {
    const float* feat = (const float*)d_in[0];
    const float* W    = (const float*)d_in[1];
    const float* b    = (const float*)d_in[2];
    float* out        = (float*)d_out;

    const int n = in_sizes[0] / (8 * 128);   // 131072
    const int tiles = n / 32;                // 128 A-rows per tile -> 4096

    cudaFuncSetAttribute(decomp_kernel, cudaFuncAttributeMaxDynamicSharedMemorySize,
                         SMEM_TOTAL);
    int dev = 0;
    cudaGetDevice(&dev);
    int sms = 148;
    cudaDeviceGetAttribute(&sms, cudaDevAttrMultiProcessorCount, dev);
    int grid = sms < tiles ? sms : tiles;

    decomp_kernel<<<grid, NTHREADS, SMEM_TOTAL>>>(feat, W, b, out, tiles);
}

// round 9
// speedup vs baseline: 1.5885x; 1.0691x over previous
#include <cuda_runtime.h>
#include <cuda_fp16.h>
#include <cstdint>

#define NTHREADS 256

// ---------------- smem layout (bytes) ----------------
// W: 256 rows x 256B (fp16) = 64KB ; A: 2 buffers x 32KB (128 rows x 256B fp16)
static constexpr int SM_WHI   = 0;
static constexpr int SM_A     = 65536;
static constexpr int A_BUF_SZ = 32768;
static constexpr int SMEM_TOTAL = 131072;

// ---------------- helpers ----------------
__device__ __forceinline__ uint32_t smem_u32(const void* p) {
    uint32_t a;
    asm("{ .reg .u64 t; cvta.to.shared.u64 t, %1; cvt.u32.u64 %0, t; }"
        : "=r"(a) : "l"(p));
    return a;
}

__device__ __forceinline__ void ldsm_x4(uint32_t& r0, uint32_t& r1,
                                        uint32_t& r2, uint32_t& r3, uint32_t addr) {
    asm volatile("ldmatrix.sync.aligned.m8n8.x4.shared.b16 {%0,%1,%2,%3}, [%4];"
                 : "=r"(r0), "=r"(r1), "=r"(r2), "=r"(r3) : "r"(addr));
}

__device__ __forceinline__ void mma_f16(float* c, const uint32_t* a,
                                        uint32_t b0, uint32_t b1) {
    asm volatile(
        "mma.sync.aligned.m16n8k16.row.col.f32.f16.f16.f32 "
        "{%0,%1,%2,%3}, {%4,%5,%6,%7}, {%8,%9}, {%0,%1,%2,%3};"
        : "+f"(c[0]), "+f"(c[1]), "+f"(c[2]), "+f"(c[3])
        : "r"(a[0]), "r"(a[1]), "r"(a[2]), "r"(a[3]), "r"(b0), "r"(b1));
}

// convert 8 consecutive fp32 -> 16B of fp16
__device__ __forceinline__ uint4 cvt8(float4 v0, float4 v1) {
    __half2 h0 = __floats2half2_rn(v0.x, v0.y);
    __half2 h1 = __floats2half2_rn(v0.z, v0.w);
    __half2 h2 = __floats2half2_rn(v1.x, v1.y);
    __half2 h3 = __floats2half2_rn(v1.z, v1.w);
    uint4 r;
    r.x = *(uint32_t*)&h0; r.y = *(uint32_t*)&h1;
    r.z = *(uint32_t*)&h2; r.w = *(uint32_t*)&h3;
    return r;
}

__device__ __forceinline__ void stcs4(float* p, float4 v) {
    asm volatile("st.global.cs.v4.f32 [%0], {%1,%2,%3,%4};"
                 :: "l"(p), "f"(v.x), "f"(v.y), "f"(v.z), "f"(v.w) : "memory");
}

// ---------------- kernel ----------------
// A = feat[::2] as [M = 4096*128, K=128] fp32 ; B = W [N=256, K=128]
// D = A_fp16 * B_fp16^T + bias  (single fp16 MMA chain, fp32 accum)
// W rows permuted within every 16 (L16 = tc*4+e*2+d -> P16 = e*8+tc*2+d) so each
// thread's epilogue fragment covers 4 consecutive output columns -> STG.128.
__global__ void __launch_bounds__(NTHREADS, 1)
decomp_kernel(const float* __restrict__ feat, const float* __restrict__ W,
              const float* __restrict__ bias, float* __restrict__ out, int num_tiles) {
    extern __shared__ char smem[];
    const uint32_t sb = smem_u32(smem);
    const int tid = threadIdx.x;
    const int lane = tid & 31;
    const int wid = tid >> 5;

    const int warp_m = wid & 1;        // 0..1  (m block of 64)
    const int warp_n = wid >> 1;       // 0..3  (n block of 64)

    // ---- stage W -> fp16 swizzled smem with column permutation (once) ----
    for (int it = 0; it < 16; it++) {
        int idx = tid + it * NTHREADS;        // 0..4095
        int L   = idx >> 4;                   // logical n row 0..255
        int ch  = idx & 15;                   // 16B fp16 chunk within row
        const float4* g = (const float4*)(W + L * 128 + ch * 8);
        uint4 h = cvt8(g[0], g[1]);
        int l16 = L & 15;
        int P = (L & ~15) | (((l16 >> 1) & 1) << 3) | ((l16 >> 2) << 1) | (l16 & 1);
        int phys = ch ^ (P & 7);
        *(uint4*)(smem + SM_WHI + P * 256 + phys * 16) = h;
    }

    // ---- preload first A tile into buf 0 (128 rows x 128 fp32 -> fp16) ----
    {
        int t0 = blockIdx.x;
#pragma unroll
        for (int it = 0; it < 8; it++) {
            int idx = tid + it * NTHREADS;    // 0..2047
            int row = idx >> 4;               // tile row 0..127
            int ch  = idx & 15;
            long f = (long)(t0 * 16 + (row >> 3)) * 2048 + (row & 7) * 128 + ch * 8;
            const float4* g = (const float4*)(feat + f);
            uint4 h = cvt8(g[0], g[1]);
            int phys = ch ^ (row & 7);
            *(uint4*)(smem + SM_A + row * 256 + phys * 16) = h;
        }
    }

    // ---- bias fragments: 4 consecutive logical cols per j (permuted map) ----
    float4 bias4[4];
#pragma unroll
    for (int j = 0; j < 4; j++) {
        int n_global = warp_n * 64 + j * 16 + (lane & 3) * 4;
        bias4[j] = *(const float4*)(bias + n_global);
    }

    // ---- per-thread ldmatrix address components ----
    const int blk = lane >> 3;          // 0..3
    const int rin = lane & 7;
    const int a_mrow_base = warp_m * 64 + ((blk & 1) << 3) + rin; // + mt*16
    const int a_khalf = blk >> 1;
    const int b_nrow_base = warp_n * 64 + ((blk >> 1) << 3) + rin; // + np*16
    const int b_khalf = blk & 1;

    const int out_h = warp_n >> 1;
    const int out_obase = (warp_n & 1) * 64;

    __syncthreads();

    int buf = 0;
    for (int t = blockIdx.x; t < num_tiles; t += gridDim.x, buf ^= 1) {
        const int tn = t + gridDim.x;
        const bool has_next = tn < num_tiles;
        const uint32_t abuf = sb + SM_A + buf * A_BUF_SZ;
        const uint32_t nbuf = (uint32_t)(SM_A + (buf ^ 1) * A_BUF_SZ);

        // ---- wave 1 of next tile's global loads (32 regs) ----
        float4 va[4][2];
        if (has_next) {
#pragma unroll
            for (int it = 0; it < 4; it++) {
                int idx = tid + it * NTHREADS;
                int row = idx >> 4;
                int ch  = idx & 15;
                long f = (long)(tn * 16 + (row >> 3)) * 2048 + (row & 7) * 128 + ch * 8;
                const float4* g = (const float4*)(feat + f);
                va[it][0] = g[0];
                va[it][1] = g[1];
            }
        }

        float c[4][8][4];
#pragma unroll
        for (int mt = 0; mt < 4; mt++)
#pragma unroll
            for (int nf = 0; nf < 8; nf++)
#pragma unroll
                for (int r = 0; r < 4; r++) c[mt][nf][r] = 0.0f;

#pragma unroll
        for (int ks = 0; ks < 8; ks++) {
            uint32_t ah[4][4];
#pragma unroll
            for (int mt = 0; mt < 4; mt++) {
                int mrow = a_mrow_base + mt * 16;
                int kc = ks * 2 + a_khalf;
                uint32_t off = (uint32_t)(mrow * 256 + (kc ^ (mrow & 7)) * 16);
                ldsm_x4(ah[mt][0], ah[mt][1], ah[mt][2], ah[mt][3], abuf + off);
            }
#pragma unroll
            for (int np = 0; np < 4; np++) {
                int nrow = b_nrow_base + np * 16;
                int kc = ks * 2 + b_khalf;
                uint32_t off = (uint32_t)(nrow * 256 + (kc ^ (nrow & 7)) * 16);
                uint32_t bh[4];
                ldsm_x4(bh[0], bh[1], bh[2], bh[3], sb + SM_WHI + off);
#pragma unroll
                for (int mt = 0; mt < 4; mt++) {
                    mma_f16(c[mt][2 * np],     ah[mt], bh[0], bh[1]);
                    mma_f16(c[mt][2 * np + 1], ah[mt], bh[2], bh[3]);
                }
            }

            // ---- mid-loop: flush wave 1, issue wave 2 (LDGs hidden under MMA) ----
            if (ks == 3 && has_next) {
#pragma unroll
                for (int it = 0; it < 4; it++) {
                    int idx = tid + it * NTHREADS;
                    int row = idx >> 4;
                    int ch  = idx & 15;
                    uint4 h = cvt8(va[it][0], va[it][1]);
                    int phys = ch ^ (row & 7);
                    *(uint4*)(smem + nbuf + row * 256 + phys * 16) = h;
                }
#pragma unroll
                for (int it = 0; it < 4; it++) {
                    int idx = tid + (it + 4) * NTHREADS;
                    int row = idx >> 4;
                    int ch  = idx & 15;
                    long f = (long)(tn * 16 + (row >> 3)) * 2048 + (row & 7) * 128 + ch * 8;
                    const float4* g = (const float4*)(feat + f);
                    va[it][0] = g[0];
                    va[it][1] = g[1];
                }
            }
        }

        // ---- flush wave 2 ----
        if (has_next) {
#pragma unroll
            for (int it = 0; it < 4; it++) {
                int idx = tid + (it + 4) * NTHREADS;
                int row = idx >> 4;
                int ch  = idx & 15;
                uint4 h = cvt8(va[it][0], va[it][1]);
                int phys = ch ^ (row & 7);
                *(uint4*)(smem + nbuf + row * 256 + phys * 16) = h;
            }
        }

        // ========== epilogue: bias + STG.128 (4 consecutive cols per thread) ====
#pragma unroll
        for (int mt = 0; mt < 4; mt++) {
            int m_local = warp_m * 64 + mt * 16 + (lane >> 2);
            long m_global = (long)t * 128 + m_local;
            long i0 = m_global >> 3;
            int ci = (int)(m_global & 7);
            long base0 = ((i0 << 4) + (out_h << 3) + ci) * 128;
#pragma unroll
            for (int j = 0; j < 4; j++) {
                int o = out_obase + j * 16 + ((lane & 3) << 2);
                float4 v0, v1;
                v0.x = c[mt][2 * j][0]     + bias4[j].x;
                v0.y = c[mt][2 * j][1]     + bias4[j].y;
                v0.z = c[mt][2 * j + 1][0] + bias4[j].z;
                v0.w = c[mt][2 * j + 1][1] + bias4[j].w;
                v1.x = c[mt][2 * j][2]     + bias4[j].x;
                v1.y = c[mt][2 * j][3]     + bias4[j].y;
                v1.z = c[mt][2 * j + 1][2] + bias4[j].z;
                v1.w = c[mt][2 * j + 1][3] + bias4[j].w;
                stcs4(out + base0 + o, v0);           // row m_local
                stcs4(out + base0 + 2048 + o, v1);    // row m_local + 8
            }
        }

        __syncthreads();
    }
}

// ---------------- launch ----------------
extern "C" void kernel_launch(void* const* d_in, const int* in_sizes, int n_in,
                              void* d_out, int out_size) {
    const float* feat = (const float*)d_in[0];
    const float* W    = (const float*)d_in[1];
    const float* b    = (const float*)d_in[2];
    float* out        = (float*)d_out;

    const int n = in_sizes[0] / (8 * 128);   // 131072
    const int tiles = n / 32;                // 128 A-rows per tile -> 4096

    cudaFuncSetAttribute(decomp_kernel, cudaFuncAttributeMaxDynamicSharedMemorySize,
                         SMEM_TOTAL);
    int dev = 0;
    cudaGetDevice(&dev);
    int sms = 148;
    cudaDeviceGetAttribute(&sms, cudaDevAttrMultiProcessorCount, dev);
    int grid = sms < tiles ? sms : tiles;

    decomp_kernel<<<grid, NTHREADS, SMEM_TOTAL>>>(feat, W, b, out, tiles);
}